// round 14
// baseline (speedup 1.0000x reference)
#include <cuda_runtime.h>
#include <cuda_fp16.h>
#include <cstdint>
#include <cstddef>

#define ALPHA 0.2f
#define L2E   1.4426950408889634f

static constexpr int BB = 4;
static constexpr int NN = 4096;
static constexpr int CC = 64;
static constexpr int NSPLIT = 4;                 // j-splits

// ---------------------------------------------------------------------------
// Scratch (__device__ globals: allocation-free rule)
// ---------------------------------------------------------------------------
__device__ __half    g_hT [BB * CC * NN];        // [b][f][n]  fp16 h^T
__device__ float     g_f1 [BB * NN];             // f1[b][n]
__device__ float     g_f2t[NN * BB];             // f2 transposed: [n][b]
__device__ uint32_t  g_adjbits[NN * 128];        // adj rows bit-packed
__device__ float     g_topv[BB * 32];            // per-batch top-32 f2 values
__device__ int       g_topj[BB * 32];            // ... and their j indices
__device__ __half    g_pC [NSPLIT * BB * NN * CC];  // fp16 partial PV per split
__device__ float     g_prs[NSPLIT * BB * NN];       // partial row sums

__device__ __forceinline__ uint32_t smem_u32(const void* p) {
    uint32_t a;
    asm("{ .reg .u64 t; cvta.to.shared.u64 t, %1; cvt.u32.u64 %0, t; }"
        : "=r"(a) : "l"(p));
    return a;
}

// pack two f32 -> f16x2 (first arg in LOW half)
__device__ __forceinline__ uint32_t pack_h2(float lo, float hi) {
    uint32_t d;
    asm("cvt.rn.f16x2.f32 %0, %1, %2;" : "=r"(d) : "f"(hi), "f"(lo));
    return d;
}

__device__ __forceinline__ void mma_f16(float c[4], uint32_t a0, uint32_t a1,
                                        uint32_t a2, uint32_t a3,
                                        uint32_t b0, uint32_t b1) {
    asm volatile(
        "mma.sync.aligned.m16n8k16.row.col.f32.f16.f16.f32 "
        "{%0,%1,%2,%3}, {%4,%5,%6,%7}, {%8,%9}, {%0,%1,%2,%3};"
        : "+f"(c[0]), "+f"(c[1]), "+f"(c[2]), "+f"(c[3])
        : "r"(a0), "r"(a1), "r"(a2), "r"(a3), "r"(b0), "r"(b1));
}

// ---------------------------------------------------------------------------
// Kernel 1: h = x@W ; f1 = h.a1 ; f2 = h.a2 ; h^T stored fp16 [b][f][n].
// 32 rows per CTA.
// ---------------------------------------------------------------------------
__global__ __launch_bounds__(256) void k_proj(const float* __restrict__ x,
                                              const float* __restrict__ W,
                                              const float* __restrict__ a)
{
    __shared__ float Ws[64][64];
    __shared__ float xs[32][64];
    __shared__ float hsm[64][17];
    __shared__ float red1[8][4], red2[8][4];

    int tid  = threadIdx.x;
    int row0 = blockIdx.x * 32;
    int bb   = row0 >> 12;
    int n0b  = row0 & (NN - 1);

#pragma unroll
    for (int t = 0; t < 16; t++) {
        int idx = tid + t * 256;
        Ws[idx >> 6][idx & 63] = W[idx];
    }
#pragma unroll
    for (int t = 0; t < 8; t++) {
        int idx = tid + t * 256;
        xs[idx >> 6][idx & 63] = x[(size_t)row0 * CC + idx];
    }
    __syncthreads();

    int slot = tid >> 6, f = tid & 63, w = tid >> 5;
    float a1v = a[f], a2v = a[64 + f];

    for (int blk = 0; blk < 2; ++blk) {
#pragma unroll
        for (int rr = 0; rr < 4; ++rr) {
            int rl = slot * 4 + rr;
            int r  = blk * 16 + rl;
            float hv = 0.f;
#pragma unroll
            for (int k = 0; k < 64; k++) hv = fmaf(xs[r][k], Ws[k][f], hv);
            hsm[f][rl] = hv;

            float v1 = hv * a1v, v2 = hv * a2v;
#pragma unroll
            for (int off = 16; off; off >>= 1) {
                v1 += __shfl_down_sync(0xffffffffu, v1, off);
                v2 += __shfl_down_sync(0xffffffffu, v2, off);
            }
            if ((tid & 31) == 0) { red1[w][rr] = v1; red2[w][rr] = v2; }
        }
        __syncthreads();

#pragma unroll
        for (int t = 0; t < 2; t++) {
            int idx = tid + t * 256;
            int ff = idx >> 3, p = idx & 7;
            float v0 = hsm[ff][2 * p], v1 = hsm[ff][2 * p + 1];
            size_t base = ((size_t)(bb * CC + ff)) * NN + n0b + blk * 16 + 2 * p;
            *(uint32_t*)(g_hT + base) = pack_h2(v0, v1);
        }
        if (tid < 16) {
            int s = tid & 3, rr = tid >> 2;
            int gg = row0 + blk * 16 + s * 4 + rr;
            g_f1[gg] = red1[2 * s][rr] + red1[2 * s + 1][rr];
            float v2 = red2[2 * s][rr] + red2[2 * s + 1][rr];
            g_f2t[(gg & (NN - 1)) * 4 + (gg >> 12)] = v2;
        }
        __syncthreads();
    }
}

// ---------------------------------------------------------------------------
// Kernel 2 (v2): per-batch top-32 of f2. Per-warp top-32 via shuffle-only
// argmax (no block syncs), then warp 0 merges the 256 candidates.
// ---------------------------------------------------------------------------
__global__ __launch_bounds__(256) void k_top32()
{
    __shared__ float cv[256];
    __shared__ int   cj[256];

    int b = blockIdx.x, tid = threadIdx.x, lane = tid & 31, wid = tid >> 5;

    float v[16];
#pragma unroll
    for (int t = 0; t < 16; t++)
        v[t] = g_f2t[(wid * 512 + t * 32 + lane) * 4 + b];

    // warp-local top-32 (descending)
    for (int it = 0; it < 32; ++it) {
        float bv = v[0]; int bt = 0;
#pragma unroll
        for (int t = 1; t < 16; t++) if (v[t] > bv) { bv = v[t]; bt = t; }
        int pos = bt * 32 + lane;               // position within warp's 512
#pragma unroll
        for (int off = 16; off; off >>= 1) {
            float ov = __shfl_down_sync(0xffffffffu, bv, off);
            int   op = __shfl_down_sync(0xffffffffu, pos, off);
            if (ov > bv) { bv = ov; pos = op; }
        }
        bv  = __shfl_sync(0xffffffffu, bv, 0);
        pos = __shfl_sync(0xffffffffu, pos, 0);
        if (lane == 0) { cv[wid * 32 + it] = bv; cj[wid * 32 + it] = wid * 512 + pos; }
        if ((pos & 31) == lane) v[pos >> 5] = -3.0e38f;
    }
    __syncthreads();

    // warp 0: top-32 of the 256 candidates
    if (wid == 0) {
        float w[8]; 
#pragma unroll
        for (int t = 0; t < 8; t++) w[t] = cv[t * 32 + lane];
        for (int it = 0; it < 32; ++it) {
            float bv = w[0]; int bt = 0;
#pragma unroll
            for (int t = 1; t < 8; t++) if (w[t] > bv) { bv = w[t]; bt = t; }
            int pos = bt * 32 + lane;
#pragma unroll
            for (int off = 16; off; off >>= 1) {
                float ov = __shfl_down_sync(0xffffffffu, bv, off);
                int   op = __shfl_down_sync(0xffffffffu, pos, off);
                if (ov > bv) { bv = ov; pos = op; }
            }
            bv  = __shfl_sync(0xffffffffu, bv, 0);
            pos = __shfl_sync(0xffffffffu, pos, 0);
            if (lane == 0) {
                g_topv[b * 32 + it] = bv;
                g_topj[b * 32 + it] = cj[pos];
            }
            if ((pos & 31) == lane) w[pos >> 5] = -3.0e38f;
        }
    }
}

// ---------------------------------------------------------------------------
// Kernel 3: adjacency bit-packing (single coalesced DRAM pass).
// ---------------------------------------------------------------------------
__global__ __launch_bounds__(256) void k_pack(const int* __restrict__ adj)
{
    int i = blockIdx.x, tid = threadIdx.x;
    int wid = tid >> 5, lane = tid & 31;
    const int* __restrict__ row = adj + ((size_t)i << 12);
#pragma unroll
    for (int t = 0; t < 16; t++) {
        int j = wid * 512 + t * 32 + lane;
        unsigned bal = __ballot_sync(0xffffffffu, row[j] > 0);
        if (lane == 0) g_adjbits[(size_t)i * 128 + wid * 16 + t] = bal;
    }
}

// ---------------------------------------------------------------------------
// Kernel 4: partial PV via fp16 mma.sync. 64 i-rows x 1024 j per CTA
// (gridDim.z=4 splits). Row max via top-32 screening in prologue.
// ---------------------------------------------------------------------------
static constexpr int TJ     = 128;
static constexpr int JSEG   = NN / NSPLIT;        // 1024
static constexpr int NCH    = JSEG / TJ;          // 8 chunks per CTA
static constexpr int BPITCH = 272;                // 128 fp16 + 16B pad
static constexpr int BPLANE = 64 * BPITCH;        // 17408 B per buffer

__global__ __launch_bounds__(128) void k_pv()
{
    __shared__ __align__(16) char bsm[2 * BPLANE];
    __shared__ float f2s[2][TJ];
    __shared__ float tv[32];
    __shared__ int   tj[32];
    __shared__ float mrow[64];

    const int tid = threadIdx.x, wid = tid >> 5, lane = tid & 31;
    const int g = lane >> 2, tg = lane & 3;
    const int b = blockIdx.y, i0 = blockIdx.x * 64;
    const int half = blockIdx.z;
    const int jbase = half * JSEG;
    const int gi0 = i0 + wid * 16 + g, gi1 = gi0 + 8;

    // ---- prologue: masked row max via top-32 screening ----
    if (tid < 32) { tv[tid] = g_topv[b * 32 + tid]; tj[tid] = g_topj[b * 32 + tid]; }
    __syncthreads();
    if (tid < 64) {
        int i = i0 + tid;
        const uint32_t* __restrict__ ab = g_adjbits + (size_t)i * 128;
        float m2 = tv[31];                       // safe overestimate fallback
#pragma unroll
        for (int k = 0; k < 32; k++) {
            int j = tj[k];
            uint32_t w = ab[j >> 5];
            if ((w >> (j & 31)) & 1u) m2 = fmaxf(m2, tv[k]);
        }
        float z = g_f1[b * NN + i] + m2;
        mrow[tid] = fmaxf(z, ALPHA * z) * L2E;   // leaky max, log2 domain
    }
    __syncthreads();

    const float mL0  = mrow[wid * 16 + g];
    const float mL1  = mrow[wid * 16 + g + 8];
    const float f1L0 = g_f1[b * NN + gi0] * L2E;
    const float f1L1 = g_f1[b * NN + gi1] * L2E;

    const uint4* bp0 = (const uint4*)(g_adjbits + (size_t)gi0 * 128 + half * 32);
    const uint4* bp1 = (const uint4*)(g_adjbits + (size_t)gi1 * 128 + half * 32);

    const uint32_t sbase  = smem_u32(bsm);
    const uint32_t f2base = smem_u32(f2s);

    auto stage = [&](int c, int buf) {
        const int jc = jbase + c * TJ;
#pragma unroll
        for (int t = 0; t < 8; t++) {
            int k = (tid << 3) + t;              // 0..1023 chunks of 16B
            int rr = k >> 4, q = k & 15;
            const __half* src = g_hT + (size_t)(b * CC + rr) * NN + jc + q * 8;
            uint32_t dst = sbase + buf * BPLANE + rr * BPITCH + q * 16;
            asm volatile("cp.async.cg.shared.global [%0], [%1], 16;"
                         :: "r"(dst), "l"(src));
        }
        {
            const float* src = g_f2t + (jc + tid) * 4 + b;
            uint32_t dst = f2base + (buf * TJ + tid) * 4;
            asm volatile("cp.async.ca.shared.global [%0], [%1], 4;"
                         :: "r"(dst), "l"(src));
        }
    };

    float C[8][4];
#pragma unroll
    for (int n = 0; n < 8; n++)
#pragma unroll
        for (int k = 0; k < 4; k++) C[n][k] = 0.f;
    float rs0 = 0.f, rs1 = 0.f;

    stage(0, 0);
    asm volatile("cp.async.commit_group;" ::: "memory");
    uint4 bits0 = bp0[0], bits1 = bp1[0];

    for (int c = 0; c < NCH; ++c) {
        const int buf = c & 1;
        if (c < NCH - 1) stage(c + 1, buf ^ 1);
        asm volatile("cp.async.commit_group;" ::: "memory");
        uint4 nb0 = bits0, nb1 = bits1;
        if (c < NCH - 1) { nb0 = bp0[c + 1]; nb1 = bp1[c + 1]; }
        asm volatile("cp.async.wait_group 1;" ::: "memory");
        __syncthreads();

        const char*  bb_ = bsm + buf * BPLANE;
        const float* f2p = f2s[buf];

#pragma unroll
        for (int ks = 0; ks < 8; ++ks) {
            const uint32_t w0 = (ks < 2) ? bits0.x : (ks < 4) ? bits0.y
                              : (ks < 6) ? bits0.z : bits0.w;
            const uint32_t w1 = (ks < 2) ? bits1.x : (ks < 4) ? bits1.y
                              : (ks < 6) ? bits1.z : bits1.w;
            const int sh = 2 * tg + 16 * (ks & 1);
            const uint32_t s0 = w0 >> sh;
            const uint32_t s1 = w1 >> sh;
            const int c0 = 2 * tg + 16 * ks;
            const float f2a = f2p[c0],     f2b = f2p[c0 + 1];
            const float f2c = f2p[c0 + 8], f2d = f2p[c0 + 9];

            float z, l, e;
#define PVAL(F1L, ML, F2) \
    (z = fmaf((F2), L2E, (F1L)), l = fmaxf(z, ALPHA * z) - (ML), \
     ({ asm("ex2.approx.f32 %0, %1;" : "=f"(e) : "f"(l)); e; }))
            float p00 = (s0 & 1u)     ? PVAL(f1L0, mL0, f2a) : 0.f;
            float p01 = (s0 & 2u)     ? PVAL(f1L0, mL0, f2b) : 0.f;
            float p02 = (s0 & 0x100u) ? PVAL(f1L0, mL0, f2c) : 0.f;
            float p03 = (s0 & 0x200u) ? PVAL(f1L0, mL0, f2d) : 0.f;
            float p10 = (s1 & 1u)     ? PVAL(f1L1, mL1, f2a) : 0.f;
            float p11 = (s1 & 2u)     ? PVAL(f1L1, mL1, f2b) : 0.f;
            float p12 = (s1 & 0x100u) ? PVAL(f1L1, mL1, f2c) : 0.f;
            float p13 = (s1 & 0x200u) ? PVAL(f1L1, mL1, f2d) : 0.f;
#undef PVAL

            rs0 += (p00 + p01) + (p02 + p03);
            rs1 += (p10 + p11) + (p12 + p13);

            uint32_t a0 = pack_h2(p00, p01);
            uint32_t a1 = pack_h2(p10, p11);
            uint32_t a2 = pack_h2(p02, p03);
            uint32_t a3 = pack_h2(p12, p13);

#pragma unroll
            for (int n0 = 0; n0 < 8; ++n0) {
                const uint32_t* rh =
                    (const uint32_t*)(bb_ + (n0 * 8 + g) * BPITCH);
                uint32_t b0 = rh[tg + 8 * ks];
                uint32_t b1 = rh[tg + 8 * ks + 4];
                mma_f16(C[n0], a0, a1, a2, a3, b0, b1);
            }
        }
        __syncthreads();
        bits0 = nb0; bits1 = nb1;
    }

    // ---- partial row sums: quad reduce over tg lanes ----
    rs0 += __shfl_xor_sync(0xffffffffu, rs0, 1);
    rs0 += __shfl_xor_sync(0xffffffffu, rs0, 2);
    rs1 += __shfl_xor_sync(0xffffffffu, rs1, 1);
    rs1 += __shfl_xor_sync(0xffffffffu, rs1, 2);
    if (tg == 0) {
        size_t base = (size_t)(half * BB + b) * NN;
        g_prs[base + gi0] = rs0;
        g_prs[base + gi1] = rs1;
    }

    // ---- store unnormalized partial C as fp16 ----
    __half* o0 = g_pC + ((size_t)(half * BB + b) * NN + gi0) * CC + 2 * tg;
    __half* o1 = g_pC + ((size_t)(half * BB + b) * NN + gi1) * CC + 2 * tg;
#pragma unroll
    for (int n0 = 0; n0 < 8; ++n0) {
        *(uint32_t*)(o0 + n0 * 8) = pack_h2(C[n0][0], C[n0][1]);
        *(uint32_t*)(o1 + n0 * 8) = pack_h2(C[n0][2], C[n0][3]);
    }
}

// ---------------------------------------------------------------------------
// Kernel 5: combine splits: out = relu(sum_q C_q / sum_q s_q)
// (same m across splits -> no rescale needed)
// ---------------------------------------------------------------------------
__global__ __launch_bounds__(256) void k_reduce(float* __restrict__ out)
{
    int e = blockIdx.x * 256 + threadIdx.x;   // quad index, 262144 total
    int row = e >> 4;                          // b*NN + n
    float s = 0.f;
#pragma unroll
    for (int q = 0; q < NSPLIT; q++) s += g_prs[(size_t)q * BB * NN + row];
    float inv = 1.0f / s;

    float accx = 0.f, accy = 0.f, accz = 0.f, accw = 0.f;
#pragma unroll
    for (int q = 0; q < NSPLIT; q++) {
        uint2 qv = ((const uint2*)(g_pC + (size_t)q * BB * NN * CC))[e];
        float2 a0 = __half22float2(*(__half2*)&qv.x);
        float2 a1 = __half22float2(*(__half2*)&qv.y);
        accx += a0.x; accy += a0.y; accz += a1.x; accw += a1.y;
    }
    float4 v;
    v.x = fmaxf(accx * inv, 0.f);
    v.y = fmaxf(accy * inv, 0.f);
    v.z = fmaxf(accz * inv, 0.f);
    v.w = fmaxf(accw * inv, 0.f);
    ((float4*)out)[e] = v;
}

// ---------------------------------------------------------------------------
extern "C" void kernel_launch(void* const* d_in, const int* in_sizes, int n_in,
                              void* d_out, int out_size)
{
    const float* x   = (const float*)d_in[0];   // [4,4096,64] f32
    const int*   adj = (const int*)  d_in[1];   // [4096,4096] i32
    const float* W   = (const float*)d_in[2];   // [64,64] f32
    const float* a   = (const float*)d_in[3];   // [128,1] f32
    float*       out = (float*)d_out;           // [4,4096,64] f32

    k_proj<<<BB * NN / 32, 256>>>(x, W, a);
    k_top32<<<BB, 256>>>();
    k_pack<<<NN, 256>>>(adj);
    dim3 grid(NN / 64, BB, NSPLIT);
    k_pv<<<grid, 128>>>();
    k_reduce<<<BB * NN * CC / 4 / 256, 256>>>(out);
}

// round 15
// speedup vs baseline: 1.2450x; 1.2450x over previous
#include <cuda_runtime.h>
#include <cuda_fp16.h>
#include <cstdint>
#include <cstddef>

#define ALPHA 0.2f
#define L2E   1.4426950408889634f

static constexpr int BB = 4;
static constexpr int NN = 4096;
static constexpr int CC = 64;
static constexpr int NSPLIT = 4;                 // j-splits

// ---------------------------------------------------------------------------
// Scratch (__device__ globals: allocation-free rule)
// NOTE: g_f1 / g_f2t hold values PRE-SCALED by log2(e).
// ---------------------------------------------------------------------------
__device__ __half    g_hT [BB * CC * NN];        // [b][f][n]  fp16 h^T
__device__ float     g_f1 [BB * NN];             // f1*L2E
__device__ float     g_f2t[NN * BB];             // f2*L2E, transposed [n][b]
__device__ uint32_t  g_adjbits[NN * 128];        // adj rows bit-packed
__device__ float     g_topv[BB * 32];            // per-batch top-32 f2L values
__device__ int       g_topj[BB * 32];            // ... and their j indices
__device__ float     g_A  [BB * NN];             // f1L - mL
__device__ float     g_A2 [BB * NN];             // 0.2*f1L - mL
__device__ __half    g_pC [NSPLIT * BB * NN * CC];  // fp16 partial PV per split
__device__ float     g_prs[NSPLIT * BB * NN];       // partial row sums

__device__ __forceinline__ uint32_t smem_u32(const void* p) {
    uint32_t a;
    asm("{ .reg .u64 t; cvta.to.shared.u64 t, %1; cvt.u32.u64 %0, t; }"
        : "=r"(a) : "l"(p));
    return a;
}

// pack two f32 -> f16x2 (first arg in LOW half)
__device__ __forceinline__ uint32_t pack_h2(float lo, float hi) {
    uint32_t d;
    asm("cvt.rn.f16x2.f32 %0, %1, %2;" : "=r"(d) : "f"(hi), "f"(lo));
    return d;
}

__device__ __forceinline__ void mma_f16(float c[4], uint32_t a0, uint32_t a1,
                                        uint32_t a2, uint32_t a3,
                                        uint32_t b0, uint32_t b1) {
    asm volatile(
        "mma.sync.aligned.m16n8k16.row.col.f32.f16.f16.f32 "
        "{%0,%1,%2,%3}, {%4,%5,%6,%7}, {%8,%9}, {%0,%1,%2,%3};"
        : "+f"(c[0]), "+f"(c[1]), "+f"(c[2]), "+f"(c[3])
        : "r"(a0), "r"(a1), "r"(a2), "r"(a3), "r"(b0), "r"(b1));
}

// ---------------------------------------------------------------------------
// Kernel 1: h = x@W ; f1 = (h.a1)*L2E ; f2 = (h.a2)*L2E ; h^T fp16 [b][f][n].
// 32 rows per CTA.
// ---------------------------------------------------------------------------
__global__ __launch_bounds__(256) void k_proj(const float* __restrict__ x,
                                              const float* __restrict__ W,
                                              const float* __restrict__ a)
{
    __shared__ float Ws[64][64];
    __shared__ float xs[32][64];
    __shared__ float hsm[64][17];
    __shared__ float red1[8][4], red2[8][4];

    int tid  = threadIdx.x;
    int row0 = blockIdx.x * 32;
    int bb   = row0 >> 12;
    int n0b  = row0 & (NN - 1);

#pragma unroll
    for (int t = 0; t < 16; t++) {
        int idx = tid + t * 256;
        Ws[idx >> 6][idx & 63] = W[idx];
    }
#pragma unroll
    for (int t = 0; t < 8; t++) {
        int idx = tid + t * 256;
        xs[idx >> 6][idx & 63] = x[(size_t)row0 * CC + idx];
    }
    __syncthreads();

    int slot = tid >> 6, f = tid & 63, w = tid >> 5;
    float a1v = a[f], a2v = a[64 + f];

    for (int blk = 0; blk < 2; ++blk) {
#pragma unroll
        for (int rr = 0; rr < 4; ++rr) {
            int rl = slot * 4 + rr;
            int r  = blk * 16 + rl;
            float hv = 0.f;
#pragma unroll
            for (int k = 0; k < 64; k++) hv = fmaf(xs[r][k], Ws[k][f], hv);
            hsm[f][rl] = hv;

            float v1 = hv * a1v, v2 = hv * a2v;
#pragma unroll
            for (int off = 16; off; off >>= 1) {
                v1 += __shfl_down_sync(0xffffffffu, v1, off);
                v2 += __shfl_down_sync(0xffffffffu, v2, off);
            }
            if ((tid & 31) == 0) { red1[w][rr] = v1; red2[w][rr] = v2; }
        }
        __syncthreads();

#pragma unroll
        for (int t = 0; t < 2; t++) {
            int idx = tid + t * 256;
            int ff = idx >> 3, p = idx & 7;
            float v0 = hsm[ff][2 * p], v1 = hsm[ff][2 * p + 1];
            size_t base = ((size_t)(bb * CC + ff)) * NN + n0b + blk * 16 + 2 * p;
            *(uint32_t*)(g_hT + base) = pack_h2(v0, v1);
        }
        if (tid < 16) {
            int s = tid & 3, rr = tid >> 2;
            int gg = row0 + blk * 16 + s * 4 + rr;
            g_f1[gg] = (red1[2 * s][rr] + red1[2 * s + 1][rr]) * L2E;
            float v2 = (red2[2 * s][rr] + red2[2 * s + 1][rr]) * L2E;
            g_f2t[(gg & (NN - 1)) * 4 + (gg >> 12)] = v2;
        }
        __syncthreads();
    }
}

// ---------------------------------------------------------------------------
// Kernel 2: per-batch top-32 of f2L. Warp-local top-32 (shuffle-only), then
// warp 0 merges 256 candidates.
// ---------------------------------------------------------------------------
__global__ __launch_bounds__(256) void k_top32()
{
    __shared__ float cv[256];
    __shared__ int   cj[256];

    int b = blockIdx.x, tid = threadIdx.x, lane = tid & 31, wid = tid >> 5;

    float v[16];
#pragma unroll
    for (int t = 0; t < 16; t++)
        v[t] = g_f2t[(wid * 512 + t * 32 + lane) * 4 + b];

    for (int it = 0; it < 32; ++it) {
        float bv = v[0]; int bt = 0;
#pragma unroll
        for (int t = 1; t < 16; t++) if (v[t] > bv) { bv = v[t]; bt = t; }
        int pos = bt * 32 + lane;
#pragma unroll
        for (int off = 16; off; off >>= 1) {
            float ov = __shfl_down_sync(0xffffffffu, bv, off);
            int   op = __shfl_down_sync(0xffffffffu, pos, off);
            if (ov > bv) { bv = ov; pos = op; }
        }
        bv  = __shfl_sync(0xffffffffu, bv, 0);
        pos = __shfl_sync(0xffffffffu, pos, 0);
        if (lane == 0) { cv[wid * 32 + it] = bv; cj[wid * 32 + it] = wid * 512 + pos; }
        if ((pos & 31) == lane) v[pos >> 5] = -3.0e38f;
    }
    __syncthreads();

    if (wid == 0) {
        float w[8];
#pragma unroll
        for (int t = 0; t < 8; t++) w[t] = cv[t * 32 + lane];
        for (int it = 0; it < 32; ++it) {
            float bv = w[0]; int bt = 0;
#pragma unroll
            for (int t = 1; t < 8; t++) if (w[t] > bv) { bv = w[t]; bt = t; }
            int pos = bt * 32 + lane;
#pragma unroll
            for (int off = 16; off; off >>= 1) {
                float ov = __shfl_down_sync(0xffffffffu, bv, off);
                int   op = __shfl_down_sync(0xffffffffu, pos, off);
                if (ov > bv) { bv = ov; pos = op; }
            }
            bv  = __shfl_sync(0xffffffffu, bv, 0);
            pos = __shfl_sync(0xffffffffu, pos, 0);
            if (lane == 0) {
                g_topv[b * 32 + it] = bv;
                g_topj[b * 32 + it] = cj[pos];
            }
            if ((pos & 31) == lane) w[pos >> 5] = -3.0e38f;
        }
    }
}

// ---------------------------------------------------------------------------
// Kernel 3: adjacency bit-packing (single coalesced DRAM pass).
// ---------------------------------------------------------------------------
__global__ __launch_bounds__(256) void k_pack(const int* __restrict__ adj)
{
    int i = blockIdx.x, tid = threadIdx.x;
    int wid = tid >> 5, lane = tid & 31;
    const int* __restrict__ row = adj + ((size_t)i << 12);
#pragma unroll
    for (int t = 0; t < 16; t++) {
        int j = wid * 512 + t * 32 + lane;
        unsigned bal = __ballot_sync(0xffffffffu, row[j] > 0);
        if (lane == 0) g_adjbits[(size_t)i * 128 + wid * 16 + t] = bal;
    }
}

// ---------------------------------------------------------------------------
// Kernel 4: per-row masked max via top-32 screening; writes per-row
// constants A = f1L - mL, A2 = 0.2*f1L - mL for k_pv.
// ---------------------------------------------------------------------------
__global__ __launch_bounds__(256) void k_mscreen()
{
    __shared__ float tv[32];
    __shared__ int   tj[32];

    int b = blockIdx.y, tid = threadIdx.x;
    int i = blockIdx.x * 256 + tid;
    if (tid < 32) { tv[tid] = g_topv[b * 32 + tid]; tj[tid] = g_topj[b * 32 + tid]; }
    __syncthreads();

    const uint32_t* __restrict__ ab = g_adjbits + (size_t)i * 128;
    float m2 = tv[31];                           // safe overestimate fallback
#pragma unroll
    for (int k = 0; k < 32; k++) {
        int j = tj[k];
        uint32_t w = ab[j >> 5];
        if ((w >> (j & 31)) & 1u) m2 = fmaxf(m2, tv[k]);
    }
    float f1L = g_f1[b * NN + i];
    float zL  = f1L + m2;
    float mL  = fmaxf(zL, ALPHA * zL);           // leaky max (log2 domain)
    g_A [b * NN + i] = f1L - mL;
    g_A2[b * NN + i] = ALPHA * f1L - mL;
}

// ---------------------------------------------------------------------------
// Kernel 5: partial PV via fp16 mma.sync. 64 i-rows x 1024 j per CTA
// (gridDim.z=4). Lean prologue (4 scalar loads) -> 6 CTAs/SM.
// ---------------------------------------------------------------------------
static constexpr int TJ     = 128;
static constexpr int JSEG   = NN / NSPLIT;        // 1024
static constexpr int NCH    = JSEG / TJ;          // 8 chunks per CTA
static constexpr int BPITCH = 272;                // 128 fp16 + 16B pad
static constexpr int BPLANE = 64 * BPITCH;        // 17408 B per buffer

__global__ __launch_bounds__(128, 6) void k_pv()
{
    __shared__ __align__(16) char bsm[2 * BPLANE];
    __shared__ float f2s[2][TJ];

    const int tid = threadIdx.x, wid = tid >> 5, lane = tid & 31;
    const int g = lane >> 2, tg = lane & 3;
    const int b = blockIdx.y, i0 = blockIdx.x * 64;
    const int half = blockIdx.z;
    const int jbase = half * JSEG;
    const int gi0 = i0 + wid * 16 + g, gi1 = gi0 + 8;

    const float A0  = g_A [b * NN + gi0];
    const float A20 = g_A2[b * NN + gi0];
    const float A1  = g_A [b * NN + gi1];
    const float A21 = g_A2[b * NN + gi1];

    const uint4* bp0 = (const uint4*)(g_adjbits + (size_t)gi0 * 128 + half * 32);
    const uint4* bp1 = (const uint4*)(g_adjbits + (size_t)gi1 * 128 + half * 32);

    const uint32_t sbase  = smem_u32(bsm);
    const uint32_t f2base = smem_u32(f2s);

    auto stage = [&](int c, int buf) {
        const int jc = jbase + c * TJ;
#pragma unroll
        for (int t = 0; t < 8; t++) {
            int k = (tid << 3) + t;              // 0..1023 chunks of 16B
            int rr = k >> 4, q = k & 15;
            const __half* src = g_hT + (size_t)(b * CC + rr) * NN + jc + q * 8;
            uint32_t dst = sbase + buf * BPLANE + rr * BPITCH + q * 16;
            asm volatile("cp.async.cg.shared.global [%0], [%1], 16;"
                         :: "r"(dst), "l"(src));
        }
        {
            const float* src = g_f2t + (jc + tid) * 4 + b;
            uint32_t dst = f2base + (buf * TJ + tid) * 4;
            asm volatile("cp.async.ca.shared.global [%0], [%1], 4;"
                         :: "r"(dst), "l"(src));
        }
    };

    float C[8][4];
#pragma unroll
    for (int n = 0; n < 8; n++)
#pragma unroll
        for (int k = 0; k < 4; k++) C[n][k] = 0.f;
    float rs0 = 0.f, rs1 = 0.f;

    stage(0, 0);
    asm volatile("cp.async.commit_group;" ::: "memory");
    uint4 bits0 = bp0[0], bits1 = bp1[0];

    for (int c = 0; c < NCH; ++c) {
        const int buf = c & 1;
        if (c < NCH - 1) stage(c + 1, buf ^ 1);
        asm volatile("cp.async.commit_group;" ::: "memory");
        uint4 nb0 = bits0, nb1 = bits1;
        if (c < NCH - 1) { nb0 = bp0[c + 1]; nb1 = bp1[c + 1]; }
        asm volatile("cp.async.wait_group 1;" ::: "memory");
        __syncthreads();

        const char*  bb_ = bsm + buf * BPLANE;
        const float* f2p = f2s[buf];

#pragma unroll
        for (int ks = 0; ks < 8; ++ks) {
            const uint32_t w0 = (ks < 2) ? bits0.x : (ks < 4) ? bits0.y
                              : (ks < 6) ? bits0.z : bits0.w;
            const uint32_t w1 = (ks < 2) ? bits1.x : (ks < 4) ? bits1.y
                              : (ks < 6) ? bits1.z : bits1.w;
            const int sh = 2 * tg + 16 * (ks & 1);
            const uint32_t s0 = w0 >> sh;
            const uint32_t s1 = w1 >> sh;
            const int c0 = 2 * tg + 16 * ks;
            const float f2a = f2p[c0],     f2b = f2p[c0 + 1];
            const float f2c = f2p[c0 + 8], f2d = f2p[c0 + 9];

            float l, e;
#define PVAL(Aa, Ab, F2L) \
    (l = fmaxf((F2L) + (Aa), fmaf((F2L), ALPHA, (Ab))), \
     ({ asm("ex2.approx.f32 %0, %1;" : "=f"(e) : "f"(l)); e; }))
            float p00 = (s0 & 1u)     ? PVAL(A0, A20, f2a) : 0.f;
            float p01 = (s0 & 2u)     ? PVAL(A0, A20, f2b) : 0.f;
            float p02 = (s0 & 0x100u) ? PVAL(A0, A20, f2c) : 0.f;
            float p03 = (s0 & 0x200u) ? PVAL(A0, A20, f2d) : 0.f;
            float p10 = (s1 & 1u)     ? PVAL(A1, A21, f2a) : 0.f;
            float p11 = (s1 & 2u)     ? PVAL(A1, A21, f2b) : 0.f;
            float p12 = (s1 & 0x100u) ? PVAL(A1, A21, f2c) : 0.f;
            float p13 = (s1 & 0x200u) ? PVAL(A1, A21, f2d) : 0.f;
#undef PVAL

            rs0 += (p00 + p01) + (p02 + p03);
            rs1 += (p10 + p11) + (p12 + p13);

            uint32_t a0 = pack_h2(p00, p01);
            uint32_t a1 = pack_h2(p10, p11);
            uint32_t a2 = pack_h2(p02, p03);
            uint32_t a3 = pack_h2(p12, p13);

#pragma unroll
            for (int n0 = 0; n0 < 8; ++n0) {
                const uint32_t* rh =
                    (const uint32_t*)(bb_ + (n0 * 8 + g) * BPITCH);
                uint32_t b0 = rh[tg + 8 * ks];
                uint32_t b1 = rh[tg + 8 * ks + 4];
                mma_f16(C[n0], a0, a1, a2, a3, b0, b1);
            }
        }
        __syncthreads();
        bits0 = nb0; bits1 = nb1;
    }

    // ---- partial row sums: quad reduce over tg lanes ----
    rs0 += __shfl_xor_sync(0xffffffffu, rs0, 1);
    rs0 += __shfl_xor_sync(0xffffffffu, rs0, 2);
    rs1 += __shfl_xor_sync(0xffffffffu, rs1, 1);
    rs1 += __shfl_xor_sync(0xffffffffu, rs1, 2);
    if (tg == 0) {
        size_t base = (size_t)(half * BB + b) * NN;
        g_prs[base + gi0] = rs0;
        g_prs[base + gi1] = rs1;
    }

    // ---- store unnormalized partial C as fp16 ----
    __half* o0 = g_pC + ((size_t)(half * BB + b) * NN + gi0) * CC + 2 * tg;
    __half* o1 = g_pC + ((size_t)(half * BB + b) * NN + gi1) * CC + 2 * tg;
#pragma unroll
    for (int n0 = 0; n0 < 8; ++n0) {
        *(uint32_t*)(o0 + n0 * 8) = pack_h2(C[n0][0], C[n0][1]);
        *(uint32_t*)(o1 + n0 * 8) = pack_h2(C[n0][2], C[n0][3]);
    }
}

// ---------------------------------------------------------------------------
// Kernel 6: combine splits: out = relu(sum_q C_q / sum_q s_q)
// (same m across splits -> no rescale needed)
// ---------------------------------------------------------------------------
__global__ __launch_bounds__(256) void k_reduce(float* __restrict__ out)
{
    int e = blockIdx.x * 256 + threadIdx.x;   // quad index, 262144 total
    int row = e >> 4;                          // b*NN + n
    float s = 0.f;
#pragma unroll
    for (int q = 0; q < NSPLIT; q++) s += g_prs[(size_t)q * BB * NN + row];
    float inv = 1.0f / s;

    float accx = 0.f, accy = 0.f, accz = 0.f, accw = 0.f;
#pragma unroll
    for (int q = 0; q < NSPLIT; q++) {
        uint2 qv = ((const uint2*)(g_pC + (size_t)q * BB * NN * CC))[e];
        float2 a0 = __half22float2(*(__half2*)&qv.x);
        float2 a1 = __half22float2(*(__half2*)&qv.y);
        accx += a0.x; accy += a0.y; accz += a1.x; accw += a1.y;
    }
    float4 v;
    v.x = fmaxf(accx * inv, 0.f);
    v.y = fmaxf(accy * inv, 0.f);
    v.z = fmaxf(accz * inv, 0.f);
    v.w = fmaxf(accw * inv, 0.f);
    ((float4*)out)[e] = v;
}

// ---------------------------------------------------------------------------
extern "C" void kernel_launch(void* const* d_in, const int* in_sizes, int n_in,
                              void* d_out, int out_size)
{
    const float* x   = (const float*)d_in[0];   // [4,4096,64] f32
    const int*   adj = (const int*)  d_in[1];   // [4096,4096] i32
    const float* W   = (const float*)d_in[2];   // [64,64] f32
    const float* a   = (const float*)d_in[3];   // [128,1] f32
    float*       out = (float*)d_out;           // [4,4096,64] f32

    k_proj<<<BB * NN / 32, 256>>>(x, W, a);
    k_top32<<<BB, 256>>>();
    k_pack<<<NN, 256>>>(adj);
    k_mscreen<<<dim3(NN / 256, BB), 256>>>();
    dim3 grid(NN / 64, BB, NSPLIT);
    k_pv<<<grid, 128>>>();
    k_reduce<<<BB * NN * CC / 4 / 256, 256>>>(out);
}

// round 17
// speedup vs baseline: 1.2467x; 1.0014x over previous
#include <cuda_runtime.h>
#include <cuda_fp16.h>
#include <cstdint>
#include <cstddef>

#define ALPHA 0.2f
#define L2E   1.4426950408889634f

static constexpr int BB = 4;
static constexpr int NN = 4096;
static constexpr int CC = 64;
static constexpr int NSPLIT = 4;                 // j-splits

// ---------------------------------------------------------------------------
// Scratch (__device__ globals: allocation-free rule)
// NOTE: g_f1 / g_f2t hold values PRE-SCALED by log2(e).
// ---------------------------------------------------------------------------
__device__ __half    g_hT [BB * CC * NN];        // [b][f][n]  fp16 h^T
__device__ float     g_f1 [BB * NN];             // f1*L2E
__device__ float     g_f2t[NN * BB];             // f2*L2E, transposed [n][b]
__device__ uint32_t  g_adjbits[NN * 128];        // adj rows bit-packed
__device__ float     g_topv[BB * 32];            // per-batch top-32 f2L values
__device__ int       g_topj[BB * 32];            // ... and their j indices
__device__ float     g_A  [BB * NN];             // f1L - mL
__device__ float     g_A2 [BB * NN];             // 0.2*f1L - mL
__device__ __half    g_pC [NSPLIT * BB * NN * CC];  // fp16 partial PV per split
__device__ float     g_prs[NSPLIT * BB * NN];       // partial row sums

__device__ __forceinline__ uint32_t smem_u32(const void* p) {
    uint32_t a;
    asm("{ .reg .u64 t; cvta.to.shared.u64 t, %1; cvt.u32.u64 %0, t; }"
        : "=r"(a) : "l"(p));
    return a;
}

// pack two f32 -> f16x2 (first arg in LOW half)
__device__ __forceinline__ uint32_t pack_h2(float lo, float hi) {
    uint32_t d;
    asm("cvt.rn.f16x2.f32 %0, %1, %2;" : "=r"(d) : "f"(hi), "f"(lo));
    return d;
}

__device__ __forceinline__ void mma_f16(float c[4], uint32_t a0, uint32_t a1,
                                        uint32_t a2, uint32_t a3,
                                        uint32_t b0, uint32_t b1) {
    asm volatile(
        "mma.sync.aligned.m16n8k16.row.col.f32.f16.f16.f32 "
        "{%0,%1,%2,%3}, {%4,%5,%6,%7}, {%8,%9}, {%0,%1,%2,%3};"
        : "+f"(c[0]), "+f"(c[1]), "+f"(c[2]), "+f"(c[3])
        : "r"(a0), "r"(a1), "r"(a2), "r"(a3), "r"(b0), "r"(b1));
}

// ---------------------------------------------------------------------------
// Kernel 1: h = x@W ; f1 = (h.a1)*L2E ; f2 = (h.a2)*L2E ; h^T fp16 [b][f][n].
// 32 rows per CTA.
// ---------------------------------------------------------------------------
__global__ __launch_bounds__(256) void k_proj(const float* __restrict__ x,
                                              const float* __restrict__ W,
                                              const float* __restrict__ a)
{
    __shared__ float Ws[64][64];
    __shared__ float xs[32][64];
    __shared__ float hsm[64][17];
    __shared__ float red1[8][4], red2[8][4];

    int tid  = threadIdx.x;
    int row0 = blockIdx.x * 32;
    int bb   = row0 >> 12;
    int n0b  = row0 & (NN - 1);

#pragma unroll
    for (int t = 0; t < 16; t++) {
        int idx = tid + t * 256;
        Ws[idx >> 6][idx & 63] = W[idx];
    }
#pragma unroll
    for (int t = 0; t < 8; t++) {
        int idx = tid + t * 256;
        xs[idx >> 6][idx & 63] = x[(size_t)row0 * CC + idx];
    }
    __syncthreads();

    int slot = tid >> 6, f = tid & 63, w = tid >> 5;
    float a1v = a[f], a2v = a[64 + f];

    for (int blk = 0; blk < 2; ++blk) {
#pragma unroll
        for (int rr = 0; rr < 4; ++rr) {
            int rl = slot * 4 + rr;
            int r  = blk * 16 + rl;
            float hv = 0.f;
#pragma unroll
            for (int k = 0; k < 64; k++) hv = fmaf(xs[r][k], Ws[k][f], hv);
            hsm[f][rl] = hv;

            float v1 = hv * a1v, v2 = hv * a2v;
#pragma unroll
            for (int off = 16; off; off >>= 1) {
                v1 += __shfl_down_sync(0xffffffffu, v1, off);
                v2 += __shfl_down_sync(0xffffffffu, v2, off);
            }
            if ((tid & 31) == 0) { red1[w][rr] = v1; red2[w][rr] = v2; }
        }
        __syncthreads();

#pragma unroll
        for (int t = 0; t < 2; t++) {
            int idx = tid + t * 256;
            int ff = idx >> 3, p = idx & 7;
            float v0 = hsm[ff][2 * p], v1 = hsm[ff][2 * p + 1];
            size_t base = ((size_t)(bb * CC + ff)) * NN + n0b + blk * 16 + 2 * p;
            *(uint32_t*)(g_hT + base) = pack_h2(v0, v1);
        }
        if (tid < 16) {
            int s = tid & 3, rr = tid >> 2;
            int gg = row0 + blk * 16 + s * 4 + rr;
            g_f1[gg] = (red1[2 * s][rr] + red1[2 * s + 1][rr]) * L2E;
            float v2 = (red2[2 * s][rr] + red2[2 * s + 1][rr]) * L2E;
            g_f2t[(gg & (NN - 1)) * 4 + (gg >> 12)] = v2;
        }
        __syncthreads();
    }
}

// ---------------------------------------------------------------------------
// Kernel 2: per-batch top-32 of f2L. Warp-local top-32 (shuffle-only), then
// warp 0 merges 256 candidates.
// ---------------------------------------------------------------------------
__global__ __launch_bounds__(256) void k_top32()
{
    __shared__ float cv[256];
    __shared__ int   cj[256];

    int b = blockIdx.x, tid = threadIdx.x, lane = tid & 31, wid = tid >> 5;

    float v[16];
#pragma unroll
    for (int t = 0; t < 16; t++)
        v[t] = g_f2t[(wid * 512 + t * 32 + lane) * 4 + b];

    for (int it = 0; it < 32; ++it) {
        float bv = v[0]; int bt = 0;
#pragma unroll
        for (int t = 1; t < 16; t++) if (v[t] > bv) { bv = v[t]; bt = t; }
        int pos = bt * 32 + lane;
#pragma unroll
        for (int off = 16; off; off >>= 1) {
            float ov = __shfl_down_sync(0xffffffffu, bv, off);
            int   op = __shfl_down_sync(0xffffffffu, pos, off);
            if (ov > bv) { bv = ov; pos = op; }
        }
        bv  = __shfl_sync(0xffffffffu, bv, 0);
        pos = __shfl_sync(0xffffffffu, pos, 0);
        if (lane == 0) { cv[wid * 32 + it] = bv; cj[wid * 32 + it] = wid * 512 + pos; }
        if ((pos & 31) == lane) v[pos >> 5] = -3.0e38f;
    }
    __syncthreads();

    if (wid == 0) {
        float w[8];
#pragma unroll
        for (int t = 0; t < 8; t++) w[t] = cv[t * 32 + lane];
        for (int it = 0; it < 32; ++it) {
            float bv = w[0]; int bt = 0;
#pragma unroll
            for (int t = 1; t < 8; t++) if (w[t] > bv) { bv = w[t]; bt = t; }
            int pos = bt * 32 + lane;
#pragma unroll
            for (int off = 16; off; off >>= 1) {
                float ov = __shfl_down_sync(0xffffffffu, bv, off);
                int   op = __shfl_down_sync(0xffffffffu, pos, off);
                if (ov > bv) { bv = ov; pos = op; }
            }
            bv  = __shfl_sync(0xffffffffu, bv, 0);
            pos = __shfl_sync(0xffffffffu, pos, 0);
            if (lane == 0) {
                g_topv[b * 32 + it] = bv;
                g_topj[b * 32 + it] = cj[pos];
            }
            if ((pos & 31) == lane) w[pos >> 5] = -3.0e38f;
        }
    }
}

// ---------------------------------------------------------------------------
// Kernel 3: adjacency bit-packing + FUSED top-32 row-max screening.
// One CTA per row i. Ballot pass streams the row (DRAM-bound); then 128
// threads probe the 128 (batch, top-k) entries (L1 hits) and reduce to the
// per-row softmax-shift constants A = f1L - mL, A2 = 0.2*f1L - mL.
// ---------------------------------------------------------------------------
__global__ __launch_bounds__(256) void k_pack(const int* __restrict__ adj)
{
    __shared__ float stv[128];
    __shared__ int   stj[128];
    __shared__ float wmax[4];

    int i = blockIdx.x, tid = threadIdx.x;
    int wid = tid >> 5, lane = tid & 31;
    const int* __restrict__ row = adj + ((size_t)i << 12);

    if (tid < 128) { stv[tid] = g_topv[tid]; stj[tid] = g_topj[tid]; }

#pragma unroll
    for (int t = 0; t < 16; t++) {
        int j = wid * 512 + t * 32 + lane;
        unsigned bal = __ballot_sync(0xffffffffu, row[j] > 0);
        if (lane == 0) g_adjbits[(size_t)i * 128 + wid * 16 + t] = bal;
    }
    __syncthreads();

    if (tid < 128) {
        int b = tid >> 5;
        int av = row[stj[tid]];                        // L1 hit (row just read)
        float cand = (av > 0) ? stv[tid] : stv[b * 32 + 31];  // fallback tv[31]
#pragma unroll
        for (int off = 16; off; off >>= 1)
            cand = fmaxf(cand, __shfl_xor_sync(0xffffffffu, cand, off));
        if (lane == 0) wmax[b] = cand;
    }
    __syncthreads();
    if (tid < BB) {
        float f1L = g_f1[tid * NN + i];
        float zL  = f1L + wmax[tid];
        float mL  = fmaxf(zL, ALPHA * zL);             // leaky max (log2 dom.)
        g_A [tid * NN + i] = f1L - mL;
        g_A2[tid * NN + i] = ALPHA * f1L - mL;
    }
}

// ---------------------------------------------------------------------------
// Kernel 4: partial PV via fp16 mma.sync. 64 i-rows x 1024 j per CTA
// (gridDim.z=4). Lean prologue (4 scalar loads) -> 6 CTAs/SM.
// ---------------------------------------------------------------------------
static constexpr int TJ     = 128;
static constexpr int JSEG   = NN / NSPLIT;        // 1024
static constexpr int NCH    = JSEG / TJ;          // 8 chunks per CTA
static constexpr int BPITCH = 272;                // 128 fp16 + 16B pad
static constexpr int BPLANE = 64 * BPITCH;        // 17408 B per buffer

__global__ __launch_bounds__(128, 6) void k_pv()
{
    __shared__ __align__(16) char bsm[2 * BPLANE];
    __shared__ float f2s[2][TJ];

    const int tid = threadIdx.x, wid = tid >> 5, lane = tid & 31;
    const int g = lane >> 2, tg = lane & 3;
    const int b = blockIdx.y, i0 = blockIdx.x * 64;
    const int half = blockIdx.z;
    const int jbase = half * JSEG;
    const int gi0 = i0 + wid * 16 + g, gi1 = gi0 + 8;

    const float A0  = g_A [b * NN + gi0];
    const float A20 = g_A2[b * NN + gi0];
    const float A1  = g_A [b * NN + gi1];
    const float A21 = g_A2[b * NN + gi1];

    const uint4* bp0 = (const uint4*)(g_adjbits + (size_t)gi0 * 128 + half * 32);
    const uint4* bp1 = (const uint4*)(g_adjbits + (size_t)gi1 * 128 + half * 32);

    const uint32_t sbase  = smem_u32(bsm);
    const uint32_t f2base = smem_u32(f2s);

    auto stage = [&](int c, int buf) {
        const int jc = jbase + c * TJ;
#pragma unroll
        for (int t = 0; t < 8; t++) {
            int k = (tid << 3) + t;              // 0..1023 chunks of 16B
            int rr = k >> 4, q = k & 15;
            const __half* src = g_hT + (size_t)(b * CC + rr) * NN + jc + q * 8;
            uint32_t dst = sbase + buf * BPLANE + rr * BPITCH + q * 16;
            asm volatile("cp.async.cg.shared.global [%0], [%1], 16;"
                         :: "r"(dst), "l"(src));
        }
        {
            const float* src = g_f2t + (jc + tid) * 4 + b;
            uint32_t dst = f2base + (buf * TJ + tid) * 4;
            asm volatile("cp.async.ca.shared.global [%0], [%1], 4;"
                         :: "r"(dst), "l"(src));
        }
    };

    float C[8][4];
#pragma unroll
    for (int n = 0; n < 8; n++)
#pragma unroll
        for (int k = 0; k < 4; k++) C[n][k] = 0.f;
    float rs0 = 0.f, rs1 = 0.f;

    stage(0, 0);
    asm volatile("cp.async.commit_group;" ::: "memory");
    uint4 bits0 = bp0[0], bits1 = bp1[0];

    for (int c = 0; c < NCH; ++c) {
        const int buf = c & 1;
        if (c < NCH - 1) stage(c + 1, buf ^ 1);
        asm volatile("cp.async.commit_group;" ::: "memory");
        uint4 nb0 = bits0, nb1 = bits1;
        if (c < NCH - 1) { nb0 = bp0[c + 1]; nb1 = bp1[c + 1]; }
        asm volatile("cp.async.wait_group 1;" ::: "memory");
        __syncthreads();

        const char*  bb_ = bsm + buf * BPLANE;
        const float* f2p = f2s[buf];

#pragma unroll
        for (int ks = 0; ks < 8; ++ks) {
            const uint32_t w0 = (ks < 2) ? bits0.x : (ks < 4) ? bits0.y
                              : (ks < 6) ? bits0.z : bits0.w;
            const uint32_t w1 = (ks < 2) ? bits1.x : (ks < 4) ? bits1.y
                              : (ks < 6) ? bits1.z : bits1.w;
            const int sh = 2 * tg + 16 * (ks & 1);
            const uint32_t s0 = w0 >> sh;
            const uint32_t s1 = w1 >> sh;
            const int c0 = 2 * tg + 16 * ks;
            const float f2a = f2p[c0],     f2b = f2p[c0 + 1];
            const float f2c = f2p[c0 + 8], f2d = f2p[c0 + 9];

            float l, e;
#define PVAL(Aa, Ab, F2L) \
    (l = fmaxf((F2L) + (Aa), fmaf((F2L), ALPHA, (Ab))), \
     ({ asm("ex2.approx.f32 %0, %1;" : "=f"(e) : "f"(l)); e; }))
            float p00 = (s0 & 1u)     ? PVAL(A0, A20, f2a) : 0.f;
            float p01 = (s0 & 2u)     ? PVAL(A0, A20, f2b) : 0.f;
            float p02 = (s0 & 0x100u) ? PVAL(A0, A20, f2c) : 0.f;
            float p03 = (s0 & 0x200u) ? PVAL(A0, A20, f2d) : 0.f;
            float p10 = (s1 & 1u)     ? PVAL(A1, A21, f2a) : 0.f;
            float p11 = (s1 & 2u)     ? PVAL(A1, A21, f2b) : 0.f;
            float p12 = (s1 & 0x100u) ? PVAL(A1, A21, f2c) : 0.f;
            float p13 = (s1 & 0x200u) ? PVAL(A1, A21, f2d) : 0.f;
#undef PVAL

            rs0 += (p00 + p01) + (p02 + p03);
            rs1 += (p10 + p11) + (p12 + p13);

            uint32_t a0 = pack_h2(p00, p01);
            uint32_t a1 = pack_h2(p10, p11);
            uint32_t a2 = pack_h2(p02, p03);
            uint32_t a3 = pack_h2(p12, p13);

#pragma unroll
            for (int n0 = 0; n0 < 8; ++n0) {
                const uint32_t* rh =
                    (const uint32_t*)(bb_ + (n0 * 8 + g) * BPITCH);
                uint32_t b0 = rh[tg + 8 * ks];
                uint32_t b1 = rh[tg + 8 * ks + 4];
                mma_f16(C[n0], a0, a1, a2, a3, b0, b1);
            }
        }
        __syncthreads();
        bits0 = nb0; bits1 = nb1;
    }

    // ---- partial row sums: quad reduce over tg lanes ----
    rs0 += __shfl_xor_sync(0xffffffffu, rs0, 1);
    rs0 += __shfl_xor_sync(0xffffffffu, rs0, 2);
    rs1 += __shfl_xor_sync(0xffffffffu, rs1, 1);
    rs1 += __shfl_xor_sync(0xffffffffu, rs1, 2);
    if (tg == 0) {
        size_t base = (size_t)(half * BB + b) * NN;
        g_prs[base + gi0] = rs0;
        g_prs[base + gi1] = rs1;
    }

    // ---- store unnormalized partial C as fp16 ----
    __half* o0 = g_pC + ((size_t)(half * BB + b) * NN + gi0) * CC + 2 * tg;
    __half* o1 = g_pC + ((size_t)(half * BB + b) * NN + gi1) * CC + 2 * tg;
#pragma unroll
    for (int n0 = 0; n0 < 8; ++n0) {
        *(uint32_t*)(o0 + n0 * 8) = pack_h2(C[n0][0], C[n0][1]);
        *(uint32_t*)(o1 + n0 * 8) = pack_h2(C[n0][2], C[n0][3]);
    }
}

// ---------------------------------------------------------------------------
// Kernel 5: combine splits: out = relu(sum_q C_q / sum_q s_q)
// (same m across splits -> no rescale needed)
// ---------------------------------------------------------------------------
__global__ __launch_bounds__(256) void k_reduce(float* __restrict__ out)
{
    int e = blockIdx.x * 256 + threadIdx.x;   // quad index, 262144 total
    int row = e >> 4;                          // b*NN + n
    float s = 0.f;
#pragma unroll
    for (int q = 0; q < NSPLIT; q++) s += g_prs[(size_t)q * BB * NN + row];
    float inv = 1.0f / s;

    float accx = 0.f, accy = 0.f, accz = 0.f, accw = 0.f;
#pragma unroll
    for (int q = 0; q < NSPLIT; q++) {
        uint2 qv = ((const uint2*)(g_pC + (size_t)q * BB * NN * CC))[e];
        float2 a0 = __half22float2(*(__half2*)&qv.x);
        float2 a1 = __half22float2(*(__half2*)&qv.y);
        accx += a0.x; accy += a0.y; accz += a1.x; accw += a1.y;
    }
    float4 v;
    v.x = fmaxf(accx * inv, 0.f);
    v.y = fmaxf(accy * inv, 0.f);
    v.z = fmaxf(accz * inv, 0.f);
    v.w = fmaxf(accw * inv, 0.f);
    ((float4*)out)[e] = v;
}

// ---------------------------------------------------------------------------
extern "C" void kernel_launch(void* const* d_in, const int* in_sizes, int n_in,
                              void* d_out, int out_size)
{
    const float* x   = (const float*)d_in[0];   // [4,4096,64] f32
    const int*   adj = (const int*)  d_in[1];   // [4096,4096] i32
    const float* W   = (const float*)d_in[2];   // [64,64] f32
    const float* a   = (const float*)d_in[3];   // [128,1] f32
    float*       out = (float*)d_out;           // [4,4096,64] f32

    k_proj<<<BB * NN / 32, 256>>>(x, W, a);
    k_top32<<<BB, 256>>>();
    k_pack<<<NN, 256>>>(adj);
    dim3 grid(NN / 64, BB, NSPLIT);
    k_pv<<<grid, 128>>>();
    k_reduce<<<BB * NN * CC / 4 / 256, 256>>>(out);
}